// round 14
// baseline (speedup 1.0000x reference)
#include <cuda_runtime.h>
#include <cuda_bf16.h>

#define KDIM  64
#define PF    4     // prefetch depth (steps)
#define NBINS 1024  // length-histogram bins (key = T - L, L >= T/2)

__device__ float g_fwd[1024];
__device__ float g_gold[1024];
__device__ int   g_done = 0;
__device__ int   g_bins[NBINS];
__device__ int   g_boff[NBINS];
__device__ int   g_bcnt[NBINS];
__device__ int   g_perm[1024];

typedef unsigned long long ull;

__device__ __forceinline__ void fma2(ull& acc, ull a, ull b) {
    asm("fma.rn.f32x2 %0, %1, %2, %3;" : "=l"(acc) : "l"(a), "l"(b), "l"(acc));
}
__device__ __forceinline__ void add2(ull& d, ull a, ull b) {
    asm("add.rn.f32x2 %0, %1, %2;" : "=l"(d) : "l"(a), "l"(b));
}
__device__ __forceinline__ float sum2(ull v) {
    return __uint_as_float((unsigned)v) + __uint_as_float((unsigned)(v >> 32));
}

// ---------- scheduling prepass: counting sort of batches by length (desc) ----------
__global__ void sched_zero() {
    g_bins[threadIdx.x] = 0;
    g_bcnt[threadIdx.x] = 0;
}
__global__ void sched_hist(const int* __restrict__ sent_len, int B, int T) {
    const int b = blockIdx.x * blockDim.x + threadIdx.x;
    if (b < B) {
        int k = T - sent_len[b];
        k = (k < 0) ? 0 : (k >= NBINS ? NBINS - 1 : k);
        atomicAdd(&g_bins[k], 1);
    }
}
__global__ void sched_scan() {            // 1 block, NBINS threads, Hillis-Steele
    __shared__ int s[NBINS];
    const int tid = threadIdx.x;
    const int mine = g_bins[tid];
    s[tid] = mine;
    __syncthreads();
    for (int off = 1; off < NBINS; off <<= 1) {
        const int v = (tid >= off) ? s[tid - off] : 0;
        __syncthreads();
        s[tid] += v;
        __syncthreads();
    }
    g_boff[tid] = s[tid] - mine;           // exclusive prefix
}
__global__ void sched_scatter(const int* __restrict__ sent_len, int B, int T) {
    const int b = blockIdx.x * blockDim.x + threadIdx.x;
    if (b < B) {
        int k = T - sent_len[b];
        k = (k < 0) ? 0 : (k >= NBINS ? NBINS - 1 : k);
        const int pos = g_boff[k] + atomicAdd(&g_bcnt[k], 1);
        g_perm[pos] = b;                   // pos 0 = longest batch
    }
}

// ---------------- gold score: one 256-thread block per batch ----------------
__global__ __launch_bounds__(256)
void crf_gold_kernel(const float* __restrict__ emis,
                     const float* __restrict__ trans,
                     const float* __restrict__ start_t,
                     const float* __restrict__ end_t,
                     const int*  __restrict__ labels,
                     const int*  __restrict__ sent_len,
                     int T)
{
    const int b   = blockIdx.x;
    const int tid = threadIdx.x;
    const int L   = sent_len[b];
    const int*   lab = labels + (size_t)b * T;
    const float* em  = emis   + (size_t)b * T * KDIM;

    float s = 0.0f;
    for (int t = tid; t < L; t += 256) {
        const int lt = lab[t];
        float v = em[(size_t)t * KDIM + lt];
        v += (t == 0) ? start_t[lt] : trans[lab[t - 1] * KDIM + lt];
        s += v;
    }
    __shared__ float ws[8];
#pragma unroll
    for (int o = 16; o; o >>= 1) s += __shfl_xor_sync(0xffffffffu, s, o);
    if ((tid & 31) == 0) ws[tid >> 5] = s;
    __syncthreads();
    if (tid < 32) {
        float u = (tid < 8) ? ws[tid] : 0.0f;
#pragma unroll
        for (int o = 4; o; o >>= 1) u += __shfl_xor_sync(0xffffffffu, u, o);
        if (tid == 0) g_gold[b] = u + end_t[lab[L - 1]];
    }
}

// ---------------- forward: 64 threads (2 warps) per batch ----------------
// Identical to R13 except the batch index comes from the length-sorted
// permutation: block k handles the k-th LONGEST batch, so the round-robin
// block->SM placement gives every SM one batch from each length quartile
// (balanced per-SM total steps).
__global__ __launch_bounds__(64, 1)
void crf_forward64(const float* __restrict__ emis,
                   const float* __restrict__ trans,
                   const float* __restrict__ start_t,
                   const float* __restrict__ end_t,
                   const int*  __restrict__ sent_len,
                   int T, int B, float* __restrict__ out)
{
    const int b = g_perm[blockIdx.x];
    const int j = threadIdx.x;
    const int L = sent_len[b];
    const float* em = emis + (size_t)b * T * KDIM;

    __shared__ __align__(16) float sa[2][KDIM];
    __shared__ float rsum[2];
    __shared__ int   sh_last;

    // E column j as 32 packed (i, i+1) f32x2 pairs -> 64 regs
    ull Epk[KDIM / 2];
#pragma unroll
    for (int i2 = 0; i2 < KDIM / 2; ++i2) {
        const float lo = __expf(trans[(2 * i2)     * KDIM + j]);
        const float hi = __expf(trans[(2 * i2 + 1) * KDIM + j]);
        Epk[i2] = (ull)__float_as_uint(lo) | ((ull)__float_as_uint(hi) << 32);
    }

    // t = 0
    float a = __expf(start_t[j] + em[j]);
    int   Stot = 0;

    // raw emission ring for steps t = 1..PF
    float er[PF];
#pragma unroll
    for (int k = 0; k < PF; ++k) {
        int tt = 1 + k; if (tt > T - 1) tt = T - 1;
        er[k] = em[(size_t)tt * KDIM + j];
    }

    int buf = 0;
    auto step = [&](float eraw) {
        const float P = __expf(eraw);      // consume-time exp (loaded PF ago)
        sa[buf][j] = a;
        __syncthreads();
        const ulonglong2* sv = (const ulonglong2*)sa[buf];
        const ulonglong2 v0 = sv[0];
        const ulonglong2 v1 = sv[1];
        const unsigned pb = (unsigned)v0.x;                  // sa[buf][0]
        const int e = (int)((pb >> 23) & 0xffu);
        const float scl = __uint_as_float((unsigned)(254 - e) << 23); // 2^(127-e)
        Stot += e - 127;
        ull a0 = 0ull, a1 = 0ull, a2 = 0ull, a3 = 0ull;
        fma2(a0, v0.x, Epk[0]);
        fma2(a1, v0.y, Epk[1]);
        fma2(a2, v1.x, Epk[2]);
        fma2(a3, v1.y, Epk[3]);
#pragma unroll
        for (int q = 1; q < 8; ++q) {
            const ulonglong2 w0 = sv[2 * q];
            const ulonglong2 w1 = sv[2 * q + 1];
            fma2(a0, w0.x, Epk[4 * q + 0]);
            fma2(a1, w0.y, Epk[4 * q + 1]);
            fma2(a2, w1.x, Epk[4 * q + 2]);
            fma2(a3, w1.y, Epk[4 * q + 3]);
        }
        add2(a0, a0, a1);
        add2(a2, a2, a3);
        add2(a0, a0, a2);
        a = sum2(a0) * scl * P;
        buf ^= 1;
    };

    int t = 1;
    for (; t + PF <= L; t += PF) {
#pragma unroll
        for (int k = 0; k < PF; ++k) {
            const float ec = er[k];
            int tp = t + PF + k; if (tp > T - 1) tp = T - 1;
            er[k] = em[(size_t)tp * KDIM + j];   // raw deep prefetch
            step(ec);
        }
    }
    for (int k = 0; t < L; ++t, ++k)             // tail: ring already filled
        step(er[k]);

    // fwd = log( sum_j a[j]*exp(end[j]) ) + Stot*ln2
    {
        float xs = a * __expf(end_t[j]);
#pragma unroll
        for (int o = 16; o; o >>= 1)
            xs += __shfl_xor_sync(0xffffffffu, xs, o);
        if ((j & 31) == 0) rsum[j >> 5] = xs;
        __syncthreads();
        if (j == 0)
            g_fwd[b] = __logf(rsum[0] + rsum[1])
                     + (float)Stot * 0.69314718055994530942f;
    }

    // ---------------- finisher: last block reduces all partials ----------------
    if (j == 0) {
        __threadfence();
        const int old = atomicAdd(&g_done, 1);
        sh_last = (old == gridDim.x - 1);
    }
    __syncthreads();
    if (sh_last) {
        __threadfence();
        float v = 0.0f;
        for (int i = j; i < B; i += 64) v += g_fwd[i] - g_gold[i];   // fixed order
#pragma unroll
        for (int o = 16; o; o >>= 1) v += __shfl_xor_sync(0xffffffffu, v, o);
        if ((j & 31) == 0) rsum[j >> 5] = v;
        __syncthreads();
        if (j == 0) {
            out[0] = (rsum[0] + rsum[1]) / (float)B;
            g_done = 0;                    // reset for next (deterministic) call
        }
    }
}

extern "C" void kernel_launch(void* const* d_in, const int* in_sizes, int n_in,
                              void* d_out, int out_size)
{
    const float* emis    = (const float*)d_in[0];
    const float* trans   = (const float*)d_in[1];
    const float* start_t = (const float*)d_in[2];
    const float* end_t   = (const float*)d_in[3];
    const int*   labels  = (const int*)d_in[4];
    const int*   slen    = (const int*)d_in[5];

    const int B = in_sizes[5];            // 512
    const int T = in_sizes[4] / B;        // 1024
    float* out = (float*)d_out;

    sched_zero<<<1, NBINS>>>();
    sched_hist<<<(B + 255) / 256, 256>>>(slen, B, T);
    sched_scan<<<1, NBINS>>>();
    sched_scatter<<<(B + 255) / 256, 256>>>(slen, B, T);
    crf_gold_kernel<<<B, 256>>>(emis, trans, start_t, end_t, labels, slen, T);
    crf_forward64<<<B, 64>>>(emis, trans, start_t, end_t, slen, T, B, out);
}

// round 15
// speedup vs baseline: 1.3657x; 1.3657x over previous
#include <cuda_runtime.h>
#include <cuda_bf16.h>

#define KDIM 64
#define PF   4   // prefetch depth (steps)

__device__ float g_fwd[1024];
__device__ float g_gold[1024];
__device__ int   g_done = 0;

typedef unsigned long long ull;

__device__ __forceinline__ void fma2(ull& acc, ull a, ull b) {
    asm("fma.rn.f32x2 %0, %1, %2, %3;" : "=l"(acc) : "l"(a), "l"(b), "l"(acc));
}
__device__ __forceinline__ void add2(ull& d, ull a, ull b) {
    asm("add.rn.f32x2 %0, %1, %2;" : "=l"(d) : "l"(a), "l"(b));
}
__device__ __forceinline__ float sum2(ull v) {
    return __uint_as_float((unsigned)v) + __uint_as_float((unsigned)(v >> 32));
}

// ---------------- gold score: one 256-thread block per batch ----------------
__global__ __launch_bounds__(256)
void crf_gold_kernel(const float* __restrict__ emis,
                     const float* __restrict__ trans,
                     const float* __restrict__ start_t,
                     const float* __restrict__ end_t,
                     const int*  __restrict__ labels,
                     const int*  __restrict__ sent_len,
                     int T)
{
    const int b   = blockIdx.x;
    const int tid = threadIdx.x;
    const int L   = sent_len[b];
    const int*   lab = labels + (size_t)b * T;
    const float* em  = emis   + (size_t)b * T * KDIM;

    float s = 0.0f;
    for (int t = tid; t < L; t += 256) {
        const int lt = lab[t];
        float v = em[(size_t)t * KDIM + lt];
        v += (t == 0) ? start_t[lt] : trans[lab[t - 1] * KDIM + lt];
        s += v;
    }
    __shared__ float ws[8];
#pragma unroll
    for (int o = 16; o; o >>= 1) s += __shfl_xor_sync(0xffffffffu, s, o);
    if ((tid & 31) == 0) ws[tid >> 5] = s;
    __syncthreads();
    if (tid < 32) {
        float u = (tid < 8) ? ws[tid] : 0.0f;
#pragma unroll
        for (int o = 4; o; o >>= 1) u += __shfl_xor_sync(0xffffffffu, u, o);
        if (tid == 0) g_gold[b] = u + end_t[lab[L - 1]];
    }
}

// ------------- forward: 128-thread block = TWO independent batches -------------
// Warps {0,1} run batch 2*bid   on SMSPs {0,1};
// warps {2,3} run batch 2*bid+1 on SMSPs {2,3}  (wid%4 mapping) —
// so all FOUR schedulers get warps (64-thread blocks left SMSP 2/3 idle).
// Each half syncs with its own NAMED barrier (64 threads), fully decoupled
// loops. Per-thread step math identical to R13: thread j owns column j,
// E = exp(trans) column in 32 packed f32x2 regs, linear-space recursion with
// exact power-of-2 renorm, raw-emission ring (exp at consume time).
__global__ __launch_bounds__(128, 1)
void crf_forward128(const float* __restrict__ emis,
                    const float* __restrict__ trans,
                    const float* __restrict__ start_t,
                    const float* __restrict__ end_t,
                    const int*  __restrict__ sent_len,
                    int T, int B, float* __restrict__ out)
{
    const int half = threadIdx.x >> 6;     // 0 or 1: which batch
    const int j    = threadIdx.x & 63;     // CRF column
    const int b    = 2 * blockIdx.x + half;
    const int L    = sent_len[b];
    const float* em = emis + (size_t)b * T * KDIM;
    const int barid = 1 + half;            // named barrier per half

    __shared__ __align__(16) float sa[2][2][KDIM];   // [half][buf][state]
    __shared__ float rsum[2][2];
    __shared__ int   sh_last;

    // E column j as 32 packed (i, i+1) f32x2 pairs -> 64 regs
    ull Epk[KDIM / 2];
#pragma unroll
    for (int i2 = 0; i2 < KDIM / 2; ++i2) {
        const float lo = __expf(trans[(2 * i2)     * KDIM + j]);
        const float hi = __expf(trans[(2 * i2 + 1) * KDIM + j]);
        Epk[i2] = (ull)__float_as_uint(lo) | ((ull)__float_as_uint(hi) << 32);
    }

    // t = 0
    float a = __expf(start_t[j] + em[j]);
    int   Stot = 0;

    // raw emission ring for steps t = 1..PF
    float er[PF];
#pragma unroll
    for (int k = 0; k < PF; ++k) {
        int tt = 1 + k; if (tt > T - 1) tt = T - 1;
        er[k] = em[(size_t)tt * KDIM + j];
    }

    int buf = 0;
    auto step = [&](float eraw) {
        const float P = __expf(eraw);      // consume-time exp (loaded PF ago)
        sa[half][buf][j] = a;
        asm volatile("bar.sync %0, 64;" :: "r"(barid) : "memory");
        const ulonglong2* sv = (const ulonglong2*)sa[half][buf];
        const ulonglong2 v0 = sv[0];
        const ulonglong2 v1 = sv[1];
        const unsigned pb = (unsigned)v0.x;                  // sa[half][buf][0]
        const int e = (int)((pb >> 23) & 0xffu);
        const float scl = __uint_as_float((unsigned)(254 - e) << 23); // 2^(127-e)
        Stot += e - 127;
        ull a0 = 0ull, a1 = 0ull, a2 = 0ull, a3 = 0ull;
        fma2(a0, v0.x, Epk[0]);
        fma2(a1, v0.y, Epk[1]);
        fma2(a2, v1.x, Epk[2]);
        fma2(a3, v1.y, Epk[3]);
#pragma unroll
        for (int q = 1; q < 8; ++q) {
            const ulonglong2 w0 = sv[2 * q];
            const ulonglong2 w1 = sv[2 * q + 1];
            fma2(a0, w0.x, Epk[4 * q + 0]);
            fma2(a1, w0.y, Epk[4 * q + 1]);
            fma2(a2, w1.x, Epk[4 * q + 2]);
            fma2(a3, w1.y, Epk[4 * q + 3]);
        }
        add2(a0, a0, a1);
        add2(a2, a2, a3);
        add2(a0, a0, a2);
        a = sum2(a0) * scl * P;
        buf ^= 1;
    };

    int t = 1;
    for (; t + PF <= L; t += PF) {
#pragma unroll
        for (int k = 0; k < PF; ++k) {
            const float ec = er[k];
            int tp = t + PF + k; if (tp > T - 1) tp = T - 1;
            er[k] = em[(size_t)tp * KDIM + j];   // raw deep prefetch
            step(ec);
        }
    }
    for (int k = 0; t < L; ++t, ++k)             // tail: ring already filled
        step(er[k]);

    // fwd = log( sum_j a[j]*exp(end[j]) ) + Stot*ln2   (per half)
    {
        float xs = a * __expf(end_t[j]);
#pragma unroll
        for (int o = 16; o; o >>= 1)
            xs += __shfl_xor_sync(0xffffffffu, xs, o);
        if ((j & 31) == 0) rsum[half][j >> 5] = xs;
        asm volatile("bar.sync %0, 64;" :: "r"(barid) : "memory");
        if (j == 0)
            g_fwd[b] = __logf(rsum[half][0] + rsum[half][1])
                     + (float)Stot * 0.69314718055994530942f;
    }

    // ---------------- finisher: last block reduces all partials ----------------
    __syncthreads();                       // both halves done, g_fwd written
    if (threadIdx.x == 0) {
        __threadfence();
        const int old = atomicAdd(&g_done, 1);
        sh_last = (old == gridDim.x - 1);
    }
    __syncthreads();
    if (sh_last) {
        __threadfence();
        float v = 0.0f;
        for (int i = threadIdx.x; i < B; i += 128) v += g_fwd[i] - g_gold[i];
#pragma unroll
        for (int o = 16; o; o >>= 1) v += __shfl_xor_sync(0xffffffffu, v, o);
        __shared__ float fin[4];
        if ((threadIdx.x & 31) == 0) fin[threadIdx.x >> 5] = v;
        __syncthreads();
        if (threadIdx.x == 0) {
            out[0] = (fin[0] + fin[1] + fin[2] + fin[3]) / (float)B;
            g_done = 0;                    // reset for next (deterministic) call
        }
    }
}

extern "C" void kernel_launch(void* const* d_in, const int* in_sizes, int n_in,
                              void* d_out, int out_size)
{
    const float* emis    = (const float*)d_in[0];
    const float* trans   = (const float*)d_in[1];
    const float* start_t = (const float*)d_in[2];
    const float* end_t   = (const float*)d_in[3];
    const int*   labels  = (const int*)d_in[4];
    const int*   slen    = (const int*)d_in[5];

    const int B = in_sizes[5];            // 512
    const int T = in_sizes[4] / B;        // 1024
    float* out = (float*)d_out;

    crf_gold_kernel<<<B, 256>>>(emis, trans, start_t, end_t, labels, slen, T);
    crf_forward128<<<B / 2, 128>>>(emis, trans, start_t, end_t, slen, T, B, out);
}

// round 16
// speedup vs baseline: 1.3974x; 1.0232x over previous
#include <cuda_runtime.h>
#include <cuda_bf16.h>

#define KDIM 64
#define PF   4   // prefetch depth (steps)

__device__ float g_fwd[1024];
__device__ float g_gold[1024];
__device__ int   g_done = 0;

typedef unsigned long long ull;

__device__ __forceinline__ void fma2(ull& acc, ull a, ull b) {
    asm("fma.rn.f32x2 %0, %1, %2, %3;" : "=l"(acc) : "l"(a), "l"(b), "l"(acc));
}
__device__ __forceinline__ void add2(ull& d, ull a, ull b) {
    asm("add.rn.f32x2 %0, %1, %2;" : "=l"(d) : "l"(a), "l"(b));
}
__device__ __forceinline__ float sum2(ull v) {
    return __uint_as_float((unsigned)v) + __uint_as_float((unsigned)(v >> 32));
}

// ---------------- gold score: one 256-thread block per batch ----------------
__global__ __launch_bounds__(256)
void crf_gold_kernel(const float* __restrict__ emis,
                     const float* __restrict__ trans,
                     const float* __restrict__ start_t,
                     const float* __restrict__ end_t,
                     const int*  __restrict__ labels,
                     const int*  __restrict__ sent_len,
                     int T)
{
    const int b   = blockIdx.x;
    const int tid = threadIdx.x;
    const int L   = sent_len[b];
    const int*   lab = labels + (size_t)b * T;
    const float* em  = emis   + (size_t)b * T * KDIM;

    float s = 0.0f;
    for (int t = tid; t < L; t += 256) {
        const int lt = lab[t];
        float v = em[(size_t)t * KDIM + lt];
        v += (t == 0) ? start_t[lt] : trans[lab[t - 1] * KDIM + lt];
        s += v;
    }
    __shared__ float ws[8];
#pragma unroll
    for (int o = 16; o; o >>= 1) s += __shfl_xor_sync(0xffffffffu, s, o);
    if ((tid & 31) == 0) ws[tid >> 5] = s;
    __syncthreads();
    if (tid < 32) {
        float u = (tid < 8) ? ws[tid] : 0.0f;
#pragma unroll
        for (int o = 4; o; o >>= 1) u += __shfl_xor_sync(0xffffffffu, u, o);
        if (tid == 0) g_gold[b] = u + end_t[lab[L - 1]];
    }
}

// ------------- forward: 128-thread block = TWO independent batches -------------
// Warps {0,1} run batch 2*bid on SMSPs {0,1}; warps {2,3} run batch 2*bid+1 on
// SMSPs {2,3}. Each half syncs with its own named barrier, fully decoupled.
// Thread j owns column j; E = exp(trans) column in 32 packed f32x2 regs.
// Linear-space recursion with exact power-of-2 renorm.
// R16: batched ring refill (4 LDGs hoisted per group, unclamped fast path),
// scl*P folded off the dependency chain.
__global__ __launch_bounds__(128, 1)
void crf_forward128(const float* __restrict__ emis,
                    const float* __restrict__ trans,
                    const float* __restrict__ start_t,
                    const float* __restrict__ end_t,
                    const int*  __restrict__ sent_len,
                    int T, int B, float* __restrict__ out)
{
    const int half = threadIdx.x >> 6;     // 0 or 1: which batch
    const int j    = threadIdx.x & 63;     // CRF column
    const int b    = 2 * blockIdx.x + half;
    const int L    = sent_len[b];
    const float* em = emis + (size_t)b * T * KDIM;
    const int barid = 1 + half;            // named barrier per half

    __shared__ __align__(16) float sa[2][2][KDIM];   // [half][buf][state]
    __shared__ float rsum[2][2];
    __shared__ int   sh_last;

    // E column j as 32 packed (i, i+1) f32x2 pairs -> 64 regs
    ull Epk[KDIM / 2];
#pragma unroll
    for (int i2 = 0; i2 < KDIM / 2; ++i2) {
        const float lo = __expf(trans[(2 * i2)     * KDIM + j]);
        const float hi = __expf(trans[(2 * i2 + 1) * KDIM + j]);
        Epk[i2] = (ull)__float_as_uint(lo) | ((ull)__float_as_uint(hi) << 32);
    }

    // t = 0
    float a = __expf(start_t[j] + em[j]);
    int   Stot = 0;

    // raw emission ring for steps t = 1..PF
    float er[PF];
#pragma unroll
    for (int k = 0; k < PF; ++k) {
        int tt = 1 + k; if (tt > T - 1) tt = T - 1;
        er[k] = em[(size_t)tt * KDIM + j];
    }

    int buf = 0;
    auto step = [&](float eraw) {
        const float P = __expf(eraw);      // consume-time exp (loaded PF ago)
        sa[half][buf][j] = a;
        asm volatile("bar.sync %0, 64;" :: "r"(barid) : "memory");
        const ulonglong2* sv = (const ulonglong2*)sa[half][buf];
        const ulonglong2 v0 = sv[0];
        const ulonglong2 v1 = sv[1];
        const unsigned pb = (unsigned)v0.x;                  // pivot = sa[..][0]
        const int e = (int)((pb >> 23) & 0xffu);
        const float scl = __uint_as_float((unsigned)(254 - e) << 23); // 2^(127-e)
        const float sp  = scl * P;         // folded off-chain (runs under FMA stream)
        Stot += e - 127;
        ull a0 = 0ull, a1 = 0ull, a2 = 0ull, a3 = 0ull;
        fma2(a0, v0.x, Epk[0]);
        fma2(a1, v0.y, Epk[1]);
        fma2(a2, v1.x, Epk[2]);
        fma2(a3, v1.y, Epk[3]);
#pragma unroll
        for (int q = 1; q < 8; ++q) {
            const ulonglong2 w0 = sv[2 * q];
            const ulonglong2 w1 = sv[2 * q + 1];
            fma2(a0, w0.x, Epk[4 * q + 0]);
            fma2(a1, w0.y, Epk[4 * q + 1]);
            fma2(a2, w1.x, Epk[4 * q + 2]);
            fma2(a3, w1.y, Epk[4 * q + 3]);
        }
        add2(a0, a0, a1);
        add2(a2, a2, a3);
        add2(a0, a0, a2);
        a = sum2(a0) * sp;
        buf ^= 1;
    };

    int t = 1;
    // fast path: refill indices t+PF .. t+2PF-1 all <= T-1, no clamping
    for (; t + PF <= L && t + 2 * PF - 1 <= T - 1; t += PF) {
        float nx[PF];
        const float* base = em + (size_t)(t + PF) * KDIM + j;
#pragma unroll
        for (int k = 0; k < PF; ++k)
            nx[k] = base[k * KDIM];        // 4 batched LDGs, MLP=4
#pragma unroll
        for (int k = 0; k < PF; ++k) {
            step(er[k]);
            er[k] = nx[k];
        }
    }
    // boundary path: clamped refill (at most ~2 groups)
    for (; t + PF <= L; t += PF) {
#pragma unroll
        for (int k = 0; k < PF; ++k) {
            const float ec = er[k];
            int tp = t + PF + k; if (tp > T - 1) tp = T - 1;
            er[k] = em[(size_t)tp * KDIM + j];
            step(ec);
        }
    }
    for (int k = 0; t < L; ++t, ++k)       // tail: ring already filled
        step(er[k]);

    // fwd = log( sum_j a[j]*exp(end[j]) ) + Stot*ln2   (per half)
    {
        float xs = a * __expf(end_t[j]);
#pragma unroll
        for (int o = 16; o; o >>= 1)
            xs += __shfl_xor_sync(0xffffffffu, xs, o);
        if ((j & 31) == 0) rsum[half][j >> 5] = xs;
        asm volatile("bar.sync %0, 64;" :: "r"(barid) : "memory");
        if (j == 0)
            g_fwd[b] = __logf(rsum[half][0] + rsum[half][1])
                     + (float)Stot * 0.69314718055994530942f;
    }

    // ---------------- finisher: last block reduces all partials ----------------
    __syncthreads();                       // both halves done, g_fwd written
    if (threadIdx.x == 0) {
        __threadfence();
        const int old = atomicAdd(&g_done, 1);
        sh_last = (old == gridDim.x - 1);
    }
    __syncthreads();
    if (sh_last) {
        __threadfence();
        float v = 0.0f;
        for (int i = threadIdx.x; i < B; i += 128) v += g_fwd[i] - g_gold[i];
#pragma unroll
        for (int o = 16; o; o >>= 1) v += __shfl_xor_sync(0xffffffffu, v, o);
        __shared__ float fin[4];
        if ((threadIdx.x & 31) == 0) fin[threadIdx.x >> 5] = v;
        __syncthreads();
        if (threadIdx.x == 0) {
            out[0] = (fin[0] + fin[1] + fin[2] + fin[3]) / (float)B;
            g_done = 0;                    // reset for next (deterministic) call
        }
    }
}

extern "C" void kernel_launch(void* const* d_in, const int* in_sizes, int n_in,
                              void* d_out, int out_size)
{
    const float* emis    = (const float*)d_in[0];
    const float* trans   = (const float*)d_in[1];
    const float* start_t = (const float*)d_in[2];
    const float* end_t   = (const float*)d_in[3];
    const int*   labels  = (const int*)d_in[4];
    const int*   slen    = (const int*)d_in[5];

    const int B = in_sizes[5];            // 512
    const int T = in_sizes[4] / B;        // 1024
    float* out = (float*)d_out;

    crf_gold_kernel<<<B, 256>>>(emis, trans, start_t, end_t, labels, slen, T);
    crf_forward128<<<B / 2, 128>>>(emis, trans, start_t, end_t, slen, T, B, out);
}